// round 13
// baseline (speedup 1.0000x reference)
#include <cuda_runtime.h>
#include <cuda_fp16.h>
#include <stdint.h>

#define B_  4
#define S_  2048
#define DM  1024
#define H_  16
#define DK  64
#define SCALEF 0.125f

// ---- device scratch (no runtime allocation allowed) ----
__device__ __half g_Q[(size_t)B_*H_*S_*DK];
__device__ __half g_K[(size_t)B_*H_*S_*DK];
__device__ __half g_V[(size_t)B_*H_*S_*DK];
__device__ __half g_ctx[(size_t)B_*S_*DM];
__device__ float  g_l[(size_t)B_*H_*S_];
__device__ __half g_S[(size_t)B_*H_*S_*S_];     // UNNORMALIZED probs exp(s)
__device__ __half g_Xh[3][(size_t)B_*S_*DM];    // half inputs
__device__ __half g_Wh[4][(size_t)DM*DM];       // half weights

// ---------- helpers ----------
__device__ __forceinline__ uint32_t h2pack(float x, float y) {
    __half2 h = __floats2half2_rn(x, y);
    return *(uint32_t*)&h;
}
__device__ __forceinline__ uint32_t sptr(const void* p) {
    return (uint32_t)__cvta_generic_to_shared(p);
}
__device__ __forceinline__ void ldsm4(uint32_t* r, uint32_t addr) {
    asm volatile("ldmatrix.sync.aligned.m8n8.x4.shared.b16 {%0,%1,%2,%3}, [%4];"
        : "=r"(r[0]), "=r"(r[1]), "=r"(r[2]), "=r"(r[3]) : "r"(addr));
}
__device__ __forceinline__ void ldsm4t(uint32_t* r, uint32_t addr) {
    asm volatile("ldmatrix.sync.aligned.m8n8.x4.trans.shared.b16 {%0,%1,%2,%3}, [%4];"
        : "=r"(r[0]), "=r"(r[1]), "=r"(r[2]), "=r"(r[3]) : "r"(addr));
}
__device__ __forceinline__ void cp16(uint32_t dst, const void* src) {
    asm volatile("cp.async.cg.shared.global [%0], [%1], 16;" :: "r"(dst), "l"(src));
}
__device__ __forceinline__ void cp_commit() {
    asm volatile("cp.async.commit_group;");
}
template <int N>
__device__ __forceinline__ void cp_wait() {
    asm volatile("cp.async.wait_group %0;" :: "n"(N));
}
__device__ __forceinline__ void mma_f16(float* c, const uint32_t* a,
                                        uint32_t b0, uint32_t b1)
{
    asm volatile(
        "mma.sync.aligned.m16n8k16.row.col.f32.f16.f16.f32 "
        "{%0,%1,%2,%3}, {%4,%5,%6,%7}, {%8,%9}, {%0,%1,%2,%3};\n"
        : "+f"(c[0]), "+f"(c[1]), "+f"(c[2]), "+f"(c[3])
        : "r"(a[0]), "r"(a[1]), "r"(a[2]), "r"(a[3]), "r"(b0), "r"(b1));
}

// ============================================================
// fp32 -> fp16 converts, batched (blockIdx.y selects tensor)
// ============================================================
__global__ __launch_bounds__(256)
void f2hX_kernel(const float* __restrict__ q, const float* __restrict__ k,
                 const float* __restrict__ v, int n8)
{
    int i = blockIdx.x * 256 + threadIdx.x;
    if (i >= n8) return;
    int which = blockIdx.y;
    const float* src = (which == 0) ? q : (which == 1) ? k : v;
    __half* dst = g_Xh[which];
    const float4* s = (const float4*)(src) + 2 * i;
    float4 a = s[0], b = s[1];
    uint4 o;
    o.x = h2pack(a.x, a.y); o.y = h2pack(a.z, a.w);
    o.z = h2pack(b.x, b.y); o.w = h2pack(b.z, b.w);
    *((uint4*)(dst) + i) = o;
}
__global__ __launch_bounds__(256)
void f2hW_kernel(const float* __restrict__ w0, const float* __restrict__ w1,
                 const float* __restrict__ w2, const float* __restrict__ w3, int n8)
{
    int i = blockIdx.x * 256 + threadIdx.x;
    if (i >= n8) return;
    int which = blockIdx.y;
    const float* src = (which == 0) ? w0 : (which == 1) ? w1
                     : (which == 2) ? w2 : w3;
    __half* dst = g_Wh[which];
    const float4* s = (const float4*)(src) + 2 * i;
    float4 a = s[0], b = s[1];
    uint4 o;
    o.x = h2pack(a.x, a.y); o.y = h2pack(a.z, a.w);
    o.z = h2pack(b.x, b.y); o.w = h2pack(b.z, b.w);
    *((uint4*)(dst) + i) = o;
}

// ============================================================
// half GEMM: 128x128 block, 4-stage cp.async ring, ONE sync/tile.
// 8 warps (2my x 4nx), warp 64m x 32n, k-tile 32.
// MODE 0: scatter half to g_Q/g_K/g_V head-split
// MODE 1: fp32 out + bias
// ============================================================
#define KP 40
#define NKT (DM / 32)
#define GNS 4                                     // pipeline stages
#define GSTAGE (128 * KP)                         // halfs per array stage
#define GEMM_SMEM (2 * GNS * GSTAGE * 2)          // bytes

template <int MODE>
__global__ __launch_bounds__(256, 2)
void gemm_h(const __half* __restrict__ X, const __half* __restrict__ W,
            const float* __restrict__ bias, float* __restrict__ Yout, int dest)
{
    extern __shared__ __half gsm[];
    __half* Xs = gsm;                  // [GNS][128][KP]
    __half* Ws = gsm + GNS * GSTAGE;   // [GNS][128][KP]

    const int tid = threadIdx.x;
    const int lane = tid & 31;
    const int gid = lane >> 2;
    const int tq  = lane & 3;
    const int lrow = lane & 7;
    const int lmat = lane >> 3;
    const int wid = tid >> 5;
    const int wm = (wid >> 2) * 64;
    const int wn = (wid & 3) * 32;
    const int m0 = blockIdx.y * 128;
    const int n0 = blockIdx.x * 128;

    const int arow = (lmat & 1) * 8 + lrow;
    const int acol = (lmat >> 1) * 8;
    const int brow = (lmat >> 1) * 8 + lrow;
    const int bcol = (lmat & 1) * 8;

    const int lr0 = tid >> 2;               // 0..63
    const int lc0 = (tid & 3) * 8;          // 0,8,16,24
    const int lr1 = lr0 + 64;               // 64..127

    float acc[4][4][4];
#pragma unroll
    for (int i = 0; i < 4; i++)
#pragma unroll
        for (int j = 0; j < 4; j++)
#pragma unroll
            for (int e = 0; e < 4; e++) acc[i][j][e] = 0.0f;

    const __half* Xb = X + (size_t)m0 * DM;
    const __half* Wb = W + (size_t)n0 * DM;

    // prologue: stages 0..GNS-2
#pragma unroll
    for (int p = 0; p < GNS - 1; p++) {
        const int k1 = p * 32;
        __half* Xst = Xs + p * GSTAGE;
        __half* Wst = Ws + p * GSTAGE;
        cp16(sptr(&Xst[lr0 * KP + lc0]), Xb + (size_t)lr0 * DM + k1 + lc0);
        cp16(sptr(&Xst[lr1 * KP + lc0]), Xb + (size_t)lr1 * DM + k1 + lc0);
        cp16(sptr(&Wst[lr0 * KP + lc0]), Wb + (size_t)lr0 * DM + k1 + lc0);
        cp16(sptr(&Wst[lr1 * KP + lc0]), Wb + (size_t)lr1 * DM + k1 + lc0);
        cp_commit();
    }

    for (int t = 0; t < NKT; t++) {
        // guarantee stage t arrived: committed-after-t = min(GNS-2, NKT-1-t)
        if (t < NKT - 2)      cp_wait<GNS - 2>();
        else if (t == NKT - 2) cp_wait<1>();
        else                   cp_wait<0>();
        __syncthreads();   // stage t visible to all; compute t-1 done -> buf (t+GNS-1)%GNS free

        if (t + GNS - 1 < NKT) {
            const int k1 = (t + GNS - 1) * 32;
            const int nb = (t + GNS - 1) % GNS;
            __half* Xst = Xs + nb * GSTAGE;
            __half* Wst = Ws + nb * GSTAGE;
            cp16(sptr(&Xst[lr0 * KP + lc0]), Xb + (size_t)lr0 * DM + k1 + lc0);
            cp16(sptr(&Xst[lr1 * KP + lc0]), Xb + (size_t)lr1 * DM + k1 + lc0);
            cp16(sptr(&Wst[lr0 * KP + lc0]), Wb + (size_t)lr0 * DM + k1 + lc0);
            cp16(sptr(&Wst[lr1 * KP + lc0]), Wb + (size_t)lr1 * DM + k1 + lc0);
            cp_commit();
        }

        const __half* Xst = Xs + (t % GNS) * GSTAGE;
        const __half* Wst = Ws + (t % GNS) * GSTAGE;
#pragma unroll
        for (int k16 = 0; k16 < 2; k16++) {
            const int kb = k16 * 16;
            uint32_t a[4][4], bf[2][4];
#pragma unroll
            for (int ms = 0; ms < 4; ms++)
                ldsm4(a[ms], sptr(&Xst[(wm + ms * 16 + arow) * KP + kb + acol]));
#pragma unroll
            for (int p = 0; p < 2; p++)
                ldsm4(bf[p], sptr(&Wst[(wn + p * 16 + brow) * KP + kb + bcol]));
#pragma unroll
            for (int ms = 0; ms < 4; ms++)
#pragma unroll
                for (int p = 0; p < 2; p++) {
                    mma_f16(acc[ms][2 * p],     a[ms], bf[p][0], bf[p][1]);
                    mma_f16(acc[ms][2 * p + 1], a[ms], bf[p][2], bf[p][3]);
                }
        }
    }

    if (MODE == 0) {
        __half* Dst = (dest == 0) ? g_Q : (dest == 1) ? g_K : g_V;
#pragma unroll
        for (int ms = 0; ms < 4; ms++) {
            int r0 = m0 + wm + ms * 16 + gid;
#pragma unroll
            for (int ns = 0; ns < 4; ns++) {
                int n = n0 + wn + ns * 8 + tq * 2;
                int h = n >> 6, dk = n & 63;
                {
                    int m = r0;
                    int b = m >> 11, s = m & 2047;
                    __half* p = Dst + (((size_t)b * H_ + h) * S_ + s) * DK + dk;
                    *(uint32_t*)p = h2pack(acc[ms][ns][0], acc[ms][ns][1]);
                }
                {
                    int m = r0 + 8;
                    int b = m >> 11, s = m & 2047;
                    __half* p = Dst + (((size_t)b * H_ + h) * S_ + s) * DK + dk;
                    *(uint32_t*)p = h2pack(acc[ms][ns][2], acc[ms][ns][3]);
                }
            }
        }
    } else {
#pragma unroll
        for (int ms = 0; ms < 4; ms++) {
            int r0 = m0 + wm + ms * 16 + gid;
#pragma unroll
            for (int ns = 0; ns < 4; ns++) {
                int n = n0 + wn + ns * 8 + tq * 2;
                float b0 = bias[n], b1 = bias[n + 1];
                *(float2*)(Yout + (size_t)r0 * DM + n) =
                    make_float2(acc[ms][ns][0] + b0, acc[ms][ns][1] + b1);
                *(float2*)(Yout + (size_t)(r0 + 8) * DM + n) =
                    make_float2(acc[ms][ns][2] + b0, acc[ms][ns][3] + b1);
            }
        }
    }
}

// ============================================================
// Flash attention v3 (unchanged from R12): no max, p to g_S.
// ============================================================
#define FKP 72
#define NT  (S_ / 64)
#define SM_K   0
#define SM_V   (2 * 64 * FKP)
#define SM_S   (4 * 64 * FKP)
#define SM_MSK (4 * 64 * FKP + 128 * FKP)
#define FLASH_SMEM (SM_MSK * 2 + 64 * 4)

__global__ __launch_bounds__(256, 2)
void flash_f16(const int* __restrict__ mask)
{
    extern __shared__ __half smh[];
    __half* KtB = smh + SM_K;
    __half* VsB = smh + SM_V;
    __half* Sst = smh + SM_S;
    int*    msk = (int*)(smh + SM_MSK);

    const int tid = threadIdx.x;
    const int lane = tid & 31;
    const int gid = lane >> 2;
    const int tq  = lane & 3;
    const int lrow = lane & 7;
    const int lmat = lane >> 3;
    const int w   = tid >> 5;
    const int qb  = blockIdx.x * 128;
    const int h   = blockIdx.y;
    const int b   = blockIdx.z;

    const int rowq0 = qb + w * 16 + gid;
    const size_t bh = (size_t)b * H_ + h;

    const int brow = (lmat >> 1) * 8 + lrow;
    const int bcol = (lmat & 1) * 8;
    const int vrow = (lmat & 1) * 8 + lrow;
    const int vcol = (lmat >> 1) * 8;

    const int key = tid >> 2;
    const int dg  = (tid & 3) * 16;

    const __half* Kg0 = g_K + bh * S_ * DK;
    const __half* Vg0 = g_V + bh * S_ * DK;

    uint32_t qa[4][4];
    {
        const __half* Qg = g_Q + (bh * S_ + qb + w * 16) * DK;
#pragma unroll
        for (int j = 0; j < 4; j++) {
            int c = j * 16 + 2 * tq;
            qa[j][0] = *(const uint32_t*)(Qg + (size_t)gid * DK + c);
            qa[j][1] = *(const uint32_t*)(Qg + (size_t)(gid + 8) * DK + c);
            qa[j][2] = *(const uint32_t*)(Qg + (size_t)gid * DK + c + 8);
            qa[j][3] = *(const uint32_t*)(Qg + (size_t)(gid + 8) * DK + c + 8);
        }
    }

    float o[8][4];
#pragma unroll
    for (int i = 0; i < 8; i++)
#pragma unroll
        for (int j = 0; j < 4; j++) o[i][j] = 0.0f;
    float l0 = 0.0f, l1 = 0.0f;

    int mreg = 0;
    if (tid < 64) mreg = mask[(size_t)b * S_ + tid];

    {
        uint32_t dK = sptr(&KtB[(size_t)key * FKP + dg]);
        uint32_t dV = sptr(&VsB[(size_t)key * FKP + dg]);
        const __half* sK = Kg0 + (size_t)key * DK + dg;
        const __half* sV = Vg0 + (size_t)key * DK + dg;
        cp16(dK, sK); cp16(dK + 16, sK + 8);
        cp16(dV, sV); cp16(dV + 16, sV + 8);
        cp_commit();
    }

    for (int t = 0; t < NT; t++) {
        const int kb64 = t * 64;
        const int buf = (t & 1) * 64;

        __syncthreads();
        if (tid < 64) msk[tid] = mreg;
        if (t + 1 < NT) {
            const int nbuf = ((t + 1) & 1) * 64;
            uint32_t dK = sptr(&KtB[(size_t)(nbuf + key) * FKP + dg]);
            uint32_t dV = sptr(&VsB[(size_t)(nbuf + key) * FKP + dg]);
            const __half* sK = Kg0 + (size_t)(kb64 + 64 + key) * DK + dg;
            const __half* sV = Vg0 + (size_t)(kb64 + 64 + key) * DK + dg;
            cp16(dK, sK); cp16(dK + 16, sK + 8);
            cp16(dV, sV); cp16(dV + 16, sV + 8);
            cp_commit();
            if (tid < 64) mreg = mask[(size_t)b * S_ + kb64 + 64 + tid];
            cp_wait<1>();
        } else {
            cp_wait<0>();
        }
        __syncthreads();

        // ---- S = Q K^T ----
        float s[8][4];
#pragma unroll
        for (int i = 0; i < 8; i++)
#pragma unroll
            for (int j = 0; j < 4; j++) s[i][j] = 0.0f;

#pragma unroll
        for (int j = 0; j < 4; j++) {
            const int kb = j * 16;
#pragma unroll
            for (int p = 0; p < 4; p++) {
                uint32_t bf[4];
                ldsm4(bf, sptr(&KtB[(size_t)(buf + p * 16 + brow) * FKP + kb + bcol]));
                mma_f16(s[2 * p],     qa[j], bf[0], bf[1]);
                mma_f16(s[2 * p + 1], qa[j], bf[2], bf[3]);
            }
        }

        // ---- p = mask ? exp(s*scale) : 0 ----
        float ss0 = 0.0f, ss1 = 0.0f;
#pragma unroll
        for (int ns = 0; ns < 8; ns++) {
            int c0 = ns * 8 + 2 * tq;
            int mk0 = msk[c0], mk1 = msk[c0 + 1];
            s[ns][0] = mk0 ? __expf(s[ns][0] * SCALEF) : 0.0f;
            s[ns][1] = mk1 ? __expf(s[ns][1] * SCALEF) : 0.0f;
            s[ns][2] = mk0 ? __expf(s[ns][2] * SCALEF) : 0.0f;
            s[ns][3] = mk1 ? __expf(s[ns][3] * SCALEF) : 0.0f;
            ss0 += s[ns][0] + s[ns][1];
            ss1 += s[ns][2] + s[ns][3];
        }
        ss0 += __shfl_xor_sync(0xffffffffu, ss0, 1);
        ss0 += __shfl_xor_sync(0xffffffffu, ss0, 2);
        ss1 += __shfl_xor_sync(0xffffffffu, ss1, 1);
        ss1 += __shfl_xor_sync(0xffffffffu, ss1, 2);
        l0 += ss0;
        l1 += ss1;

        // ---- P fragments ----
        uint32_t pa[4][4];
#pragma unroll
        for (int j = 0; j < 4; j++) {
            pa[j][0] = h2pack(s[2 * j][0], s[2 * j][1]);
            pa[j][1] = h2pack(s[2 * j][2], s[2 * j][3]);
            pa[j][2] = h2pack(s[2 * j + 1][0], s[2 * j + 1][1]);
            pa[j][3] = h2pack(s[2 * j + 1][2], s[2 * j + 1][3]);
        }

        // stage p into Sst (warp-local rows)
#pragma unroll
        for (int j = 0; j < 4; j++) {
            *(uint32_t*)&Sst[(size_t)(w * 16 + gid) * FKP + (2 * j) * 8 + 2 * tq]     = pa[j][0];
            *(uint32_t*)&Sst[(size_t)(w * 16 + gid) * FKP + (2 * j + 1) * 8 + 2 * tq] = pa[j][2];
            *(uint32_t*)&Sst[(size_t)(w * 16 + gid + 8) * FKP + (2 * j) * 8 + 2 * tq]     = pa[j][1];
            *(uint32_t*)&Sst[(size_t)(w * 16 + gid + 8) * FKP + (2 * j + 1) * 8 + 2 * tq] = pa[j][3];
        }
        __syncthreads();

        // cooperative coalesced store of p tile
#pragma unroll
        for (int i = 0; i < 4; i++) {
            int idx = tid + i * 256;
            int row = idx >> 3;
            int c8 = (idx & 7) * 8;
            uint4 v = *(uint4*)&Sst[(size_t)row * FKP + c8];
            *(uint4*)(g_S + (bh * S_ + qb + row) * S_ + kb64 + c8) = v;
        }

        // ---- O += P V ----
#pragma unroll
        for (int j = 0; j < 4; j++) {
#pragma unroll
            for (int p = 0; p < 4; p++) {
                uint32_t vf[4];
                ldsm4t(vf, sptr(&VsB[(size_t)(buf + j * 16 + vrow) * FKP + p * 16 + vcol]));
                mma_f16(o[2 * p],     pa[j], vf[0], vf[1]);
                mma_f16(o[2 * p + 1], pa[j], vf[2], vf[3]);
            }
        }
    }

    float inv0 = 1.0f / l0, inv1 = 1.0f / l1;
#pragma unroll
    for (int ds = 0; ds < 8; ds++) {
        int dv = ds * 8 + tq * 2;
        __half* p0 = g_ctx + (((size_t)b * S_ + rowq0) * H_ + h) * DK + dv;
        __half* p1 = g_ctx + (((size_t)b * S_ + rowq0 + 8) * H_ + h) * DK + dv;
        *(uint32_t*)p0 = h2pack(o[ds][0] * inv0, o[ds][1] * inv0);
        *(uint32_t*)p1 = h2pack(o[ds][2] * inv1, o[ds][3] * inv1);
    }
    if (tq == 0) {
        g_l[bh * S_ + rowq0] = l0;
        g_l[bh * S_ + rowq0 + 8] = l1;
    }
}

// ============================================================
// Mean over heads: pure streaming p * (1/l), no exp.
// ============================================================
__global__ __launch_bounds__(256)
void mean_pass(float* __restrict__ outm)
{
    __shared__ float sl[H_];
    const int tid = threadIdx.x;
    const int q = blockIdx.x;
    const int b = blockIdx.y;

    if (tid < H_)
        sl[tid] = 1.0f / g_l[((size_t)b * H_ + tid) * S_ + q];
    __syncthreads();

    const int k0 = tid * 8;
    float acc[8];
#pragma unroll
    for (int i = 0; i < 8; i++) acc[i] = 0.0f;

    for (int h = 0; h < H_; h++) {
        const __half* Sp = g_S + (((size_t)b * H_ + h) * S_ + q) * S_ + k0;
        uint4 raw = *(const uint4*)Sp;
        const __half2* hp = (const __half2*)&raw;
        float lih = sl[h];
#pragma unroll
        for (int i = 0; i < 4; i++) {
            float2 v = __half22float2(hp[i]);
            acc[2 * i + 0] += v.x * lih;
            acc[2 * i + 1] += v.y * lih;
        }
    }

    const float invH = 1.0f / (float)H_;
    float* op = outm + ((size_t)b * S_ + q) * S_ + k0;
    *(float4*)op = make_float4(acc[0]*invH, acc[1]*invH, acc[2]*invH, acc[3]*invH);
    *(float4*)(op + 4) = make_float4(acc[4]*invH, acc[5]*invH, acc[6]*invH, acc[7]*invH);
}

// ============================================================
extern "C" void kernel_launch(void* const* d_in, const int* in_sizes, int n_in,
                              void* d_out, int out_size)
{
    const float* query = (const float*)d_in[0];
    const float* keyt  = (const float*)d_in[1];
    const float* value = (const float*)d_in[2];
    const int*   mask  = (const int*)d_in[3];
    const float* Wq    = (const float*)d_in[4];
    const float* Wk    = (const float*)d_in[5];
    const float* Wv    = (const float*)d_in[6];
    const float* Wo    = (const float*)d_in[7];
    const float* bo    = (const float*)d_in[8];
    float* out = (float*)d_out;

    cudaFuncSetAttribute(flash_f16,
                         cudaFuncAttributeMaxDynamicSharedMemorySize, FLASH_SMEM);
    cudaFuncSetAttribute(gemm_h<0>,
                         cudaFuncAttributeMaxDynamicSharedMemorySize, GEMM_SMEM);
    cudaFuncSetAttribute(gemm_h<1>,
                         cudaFuncAttributeMaxDynamicSharedMemorySize, GEMM_SMEM);

    __half *xh0, *xh1, *xh2, *wh0, *wh1, *wh2, *wh3;
    cudaGetSymbolAddress((void**)&xh0, g_Xh);
    xh1 = xh0 + (size_t)B_ * S_ * DM;
    xh2 = xh1 + (size_t)B_ * S_ * DM;
    cudaGetSymbolAddress((void**)&wh0, g_Wh);
    wh1 = wh0 + (size_t)DM * DM;
    wh2 = wh1 + (size_t)DM * DM;
    wh3 = wh2 + (size_t)DM * DM;

    const int nX8 = (B_ * S_ * DM) / 8;
    const int nW8 = (DM * DM) / 8;
    f2hX_kernel<<<dim3((nX8 + 255) / 256, 3), 256>>>(query, keyt, value, nX8);
    f2hW_kernel<<<dim3((nW8 + 255) / 256, 4), 256>>>(Wq, Wk, Wv, Wo, nW8);

    dim3 gg(DM / 128, (B_ * S_) / 128);
    gemm_h<0><<<gg, 256, GEMM_SMEM>>>(xh0, wh0, nullptr, nullptr, 0);
    gemm_h<0><<<gg, 256, GEMM_SMEM>>>(xh1, wh1, nullptr, nullptr, 1);
    gemm_h<0><<<gg, 256, GEMM_SMEM>>>(xh2, wh2, nullptr, nullptr, 2);

    flash_f16<<<dim3(S_ / 128, H_, B_), 256, FLASH_SMEM>>>(mask);

    __half* ctxp;
    cudaGetSymbolAddress((void**)&ctxp, g_ctx);
    gemm_h<1><<<gg, 256, GEMM_SMEM>>>(ctxp, wh3, bo, out, 3);

    long long need = (long long)B_ * S_ * DM + (long long)B_ * S_ * S_;
    if ((long long)out_size >= need) {
        mean_pass<<<dim3(S_, B_), 256>>>(out + (size_t)B_ * S_ * DM);
    }
}

// round 15
// speedup vs baseline: 1.4978x; 1.4978x over previous
#include <cuda_runtime.h>
#include <cuda_fp16.h>
#include <stdint.h>

#define B_  4
#define S_  2048
#define DM  1024
#define H_  16
#define DK  64
#define SCALEF 0.125f

// ---- device scratch (no runtime allocation allowed) ----
__device__ __half g_Q[(size_t)B_*H_*S_*DK];
__device__ __half g_K[(size_t)B_*H_*S_*DK];
__device__ __half g_V[(size_t)B_*H_*S_*DK];
__device__ __half g_ctx[(size_t)B_*S_*DM];
__device__ float  g_l[(size_t)B_*H_*S_];
__device__ __half g_S[(size_t)B_*H_*S_*S_];     // UNNORMALIZED probs exp(s)
__device__ __half g_Xh[3][(size_t)B_*S_*DM];    // half inputs
__device__ __half g_Wh[4][(size_t)DM*DM];       // half weights

// ---------- helpers ----------
__device__ __forceinline__ uint32_t h2pack(float x, float y) {
    __half2 h = __floats2half2_rn(x, y);
    return *(uint32_t*)&h;
}
__device__ __forceinline__ uint32_t sptr(const void* p) {
    return (uint32_t)__cvta_generic_to_shared(p);
}
__device__ __forceinline__ void ldsm4(uint32_t* r, uint32_t addr) {
    asm volatile("ldmatrix.sync.aligned.m8n8.x4.shared.b16 {%0,%1,%2,%3}, [%4];"
        : "=r"(r[0]), "=r"(r[1]), "=r"(r[2]), "=r"(r[3]) : "r"(addr));
}
__device__ __forceinline__ void ldsm4t(uint32_t* r, uint32_t addr) {
    asm volatile("ldmatrix.sync.aligned.m8n8.x4.trans.shared.b16 {%0,%1,%2,%3}, [%4];"
        : "=r"(r[0]), "=r"(r[1]), "=r"(r[2]), "=r"(r[3]) : "r"(addr));
}
__device__ __forceinline__ void cp16(uint32_t dst, const void* src) {
    asm volatile("cp.async.cg.shared.global [%0], [%1], 16;" :: "r"(dst), "l"(src));
}
__device__ __forceinline__ void cp_commit() {
    asm volatile("cp.async.commit_group;");
}
template <int N>
__device__ __forceinline__ void cp_wait() {
    asm volatile("cp.async.wait_group %0;" :: "n"(N));
}
__device__ __forceinline__ void mma_f16(float* c, const uint32_t* a,
                                        uint32_t b0, uint32_t b1)
{
    asm volatile(
        "mma.sync.aligned.m16n8k16.row.col.f32.f16.f16.f32 "
        "{%0,%1,%2,%3}, {%4,%5,%6,%7}, {%8,%9}, {%0,%1,%2,%3};\n"
        : "+f"(c[0]), "+f"(c[1]), "+f"(c[2]), "+f"(c[3])
        : "r"(a[0]), "r"(a[1]), "r"(a[2]), "r"(a[3]), "r"(b0), "r"(b1));
}

// ============================================================
// fp32 -> fp16 converts, batched (blockIdx.y selects tensor)
// ============================================================
__global__ __launch_bounds__(256)
void f2hX_kernel(const float* __restrict__ q, const float* __restrict__ k,
                 const float* __restrict__ v, int n8)
{
    int i = blockIdx.x * 256 + threadIdx.x;
    if (i >= n8) return;
    int which = blockIdx.y;
    const float* src = (which == 0) ? q : (which == 1) ? k : v;
    __half* dst = g_Xh[which];
    const float4* s = (const float4*)(src) + 2 * i;
    float4 a = s[0], b = s[1];
    uint4 o;
    o.x = h2pack(a.x, a.y); o.y = h2pack(a.z, a.w);
    o.z = h2pack(b.x, b.y); o.w = h2pack(b.z, b.w);
    *((uint4*)(dst) + i) = o;
}
__global__ __launch_bounds__(256)
void f2hW_kernel(const float* __restrict__ w0, const float* __restrict__ w1,
                 const float* __restrict__ w2, const float* __restrict__ w3, int n8)
{
    int i = blockIdx.x * 256 + threadIdx.x;
    if (i >= n8) return;
    int which = blockIdx.y;
    const float* src = (which == 0) ? w0 : (which == 1) ? w1
                     : (which == 2) ? w2 : w3;
    __half* dst = g_Wh[which];
    const float4* s = (const float4*)(src) + 2 * i;
    float4 a = s[0], b = s[1];
    uint4 o;
    o.x = h2pack(a.x, a.y); o.y = h2pack(a.z, a.w);
    o.z = h2pack(b.x, b.y); o.w = h2pack(b.z, b.w);
    *((uint4*)(dst) + i) = o;
}

// ============================================================
// half GEMM (R12-proven 2-stage): 128x128, cp.async dbuf.
// MODE 0: fused 3-projection launch; blockIdx.z selects X/W/dest.
// MODE 1: g_ctx @ Wo^T -> fp32 out + bias
// ============================================================
#define KP 40
#define NKT (DM / 32)
template <int MODE>
__global__ __launch_bounds__(256)
void gemm_h(const __half* __restrict__ Xp, const __half* __restrict__ Wp,
            const float* __restrict__ bias, float* __restrict__ Yout)
{
    __shared__ __half Xs[2][128][KP];
    __shared__ __half Ws[2][128][KP];

    const int tid = threadIdx.x;
    const int lane = tid & 31;
    const int gid = lane >> 2;
    const int tq  = lane & 3;
    const int lrow = lane & 7;
    const int lmat = lane >> 3;
    const int wid = tid >> 5;
    const int wm = (wid >> 2) * 64;
    const int wn = (wid & 3) * 32;
    const int m0 = blockIdx.y * 128;
    const int n0 = blockIdx.x * 128;
    const int dest = (MODE == 0) ? blockIdx.z : 3;

    const __half* X = (MODE == 0) ? g_Xh[dest] : Xp;
    const __half* W = (MODE == 0) ? g_Wh[dest] : Wp;

    const int arow = (lmat & 1) * 8 + lrow;
    const int acol = (lmat >> 1) * 8;
    const int brow = (lmat >> 1) * 8 + lrow;
    const int bcol = (lmat & 1) * 8;

    const int lr0 = tid >> 2;
    const int lc0 = (tid & 3) * 8;
    const int lr1 = lr0 + 64;

    float acc[4][4][4];
#pragma unroll
    for (int i = 0; i < 4; i++)
#pragma unroll
        for (int j = 0; j < 4; j++)
#pragma unroll
            for (int e = 0; e < 4; e++) acc[i][j][e] = 0.0f;

    const __half* Xb = X + (size_t)m0 * DM;
    const __half* Wb = W + (size_t)n0 * DM;

    {
        cp16(sptr(&Xs[0][lr0][lc0]), Xb + (size_t)lr0 * DM + lc0);
        cp16(sptr(&Xs[0][lr1][lc0]), Xb + (size_t)lr1 * DM + lc0);
        cp16(sptr(&Ws[0][lr0][lc0]), Wb + (size_t)lr0 * DM + lc0);
        cp16(sptr(&Ws[0][lr1][lc0]), Wb + (size_t)lr1 * DM + lc0);
        cp_commit();
    }

    for (int t = 0; t < NKT; t++) {
        const int buf = t & 1;
        __syncthreads();
        if (t + 1 < NKT) {
            const int nb = buf ^ 1;
            const int k1 = (t + 1) * 32;
            cp16(sptr(&Xs[nb][lr0][lc0]), Xb + (size_t)lr0 * DM + k1 + lc0);
            cp16(sptr(&Xs[nb][lr1][lc0]), Xb + (size_t)lr1 * DM + k1 + lc0);
            cp16(sptr(&Ws[nb][lr0][lc0]), Wb + (size_t)lr0 * DM + k1 + lc0);
            cp16(sptr(&Ws[nb][lr1][lc0]), Wb + (size_t)lr1 * DM + k1 + lc0);
            cp_commit();
            cp_wait<1>();
        } else {
            cp_wait<0>();
        }
        __syncthreads();

#pragma unroll
        for (int k16 = 0; k16 < 2; k16++) {
            const int kb = k16 * 16;
            uint32_t a[4][4], bf[2][4];
#pragma unroll
            for (int ms = 0; ms < 4; ms++)
                ldsm4(a[ms], sptr(&Xs[buf][wm + ms * 16 + arow][kb + acol]));
#pragma unroll
            for (int p = 0; p < 2; p++)
                ldsm4(bf[p], sptr(&Ws[buf][wn + p * 16 + brow][kb + bcol]));
#pragma unroll
            for (int ms = 0; ms < 4; ms++)
#pragma unroll
                for (int p = 0; p < 2; p++) {
                    mma_f16(acc[ms][2 * p],     a[ms], bf[p][0], bf[p][1]);
                    mma_f16(acc[ms][2 * p + 1], a[ms], bf[p][2], bf[p][3]);
                }
        }
    }

    if (MODE == 0) {
        __half* Dst = (dest == 0) ? g_Q : (dest == 1) ? g_K : g_V;
#pragma unroll
        for (int ms = 0; ms < 4; ms++) {
            int r0 = m0 + wm + ms * 16 + gid;
#pragma unroll
            for (int ns = 0; ns < 4; ns++) {
                int n = n0 + wn + ns * 8 + tq * 2;
                int h = n >> 6, dk = n & 63;
                {
                    int m = r0;
                    int b = m >> 11, s = m & 2047;
                    __half* p = Dst + (((size_t)b * H_ + h) * S_ + s) * DK + dk;
                    *(uint32_t*)p = h2pack(acc[ms][ns][0], acc[ms][ns][1]);
                }
                {
                    int m = r0 + 8;
                    int b = m >> 11, s = m & 2047;
                    __half* p = Dst + (((size_t)b * H_ + h) * S_ + s) * DK + dk;
                    *(uint32_t*)p = h2pack(acc[ms][ns][2], acc[ms][ns][3]);
                }
            }
        }
    } else {
#pragma unroll
        for (int ms = 0; ms < 4; ms++) {
            int r0 = m0 + wm + ms * 16 + gid;
#pragma unroll
            for (int ns = 0; ns < 4; ns++) {
                int n = n0 + wn + ns * 8 + tq * 2;
                float b0 = bias[n], b1 = bias[n + 1];
                *(float2*)(Yout + (size_t)r0 * DM + n) =
                    make_float2(acc[ms][ns][0] + b0, acc[ms][ns][1] + b1);
                *(float2*)(Yout + (size_t)(r0 + 8) * DM + n) =
                    make_float2(acc[ms][ns][2] + b0, acc[ms][ns][3] + b1);
            }
        }
    }
}

// ============================================================
// Flash attention v3 (unchanged from R12): no max, p to g_S.
// ============================================================
#define FKP 72
#define NT  (S_ / 64)
#define SM_K   0
#define SM_V   (2 * 64 * FKP)
#define SM_S   (4 * 64 * FKP)
#define SM_MSK (4 * 64 * FKP + 128 * FKP)
#define FLASH_SMEM (SM_MSK * 2 + 64 * 4)

__global__ __launch_bounds__(256, 2)
void flash_f16(const int* __restrict__ mask)
{
    extern __shared__ __half smh[];
    __half* KtB = smh + SM_K;
    __half* VsB = smh + SM_V;
    __half* Sst = smh + SM_S;
    int*    msk = (int*)(smh + SM_MSK);

    const int tid = threadIdx.x;
    const int lane = tid & 31;
    const int gid = lane >> 2;
    const int tq  = lane & 3;
    const int lrow = lane & 7;
    const int lmat = lane >> 3;
    const int w   = tid >> 5;
    const int qb  = blockIdx.x * 128;
    const int h   = blockIdx.y;
    const int b   = blockIdx.z;

    const int rowq0 = qb + w * 16 + gid;
    const size_t bh = (size_t)b * H_ + h;

    const int brow = (lmat >> 1) * 8 + lrow;
    const int bcol = (lmat & 1) * 8;
    const int vrow = (lmat & 1) * 8 + lrow;
    const int vcol = (lmat >> 1) * 8;

    const int key = tid >> 2;
    const int dg  = (tid & 3) * 16;

    const __half* Kg0 = g_K + bh * S_ * DK;
    const __half* Vg0 = g_V + bh * S_ * DK;

    uint32_t qa[4][4];
    {
        const __half* Qg = g_Q + (bh * S_ + qb + w * 16) * DK;
#pragma unroll
        for (int j = 0; j < 4; j++) {
            int c = j * 16 + 2 * tq;
            qa[j][0] = *(const uint32_t*)(Qg + (size_t)gid * DK + c);
            qa[j][1] = *(const uint32_t*)(Qg + (size_t)(gid + 8) * DK + c);
            qa[j][2] = *(const uint32_t*)(Qg + (size_t)gid * DK + c + 8);
            qa[j][3] = *(const uint32_t*)(Qg + (size_t)(gid + 8) * DK + c + 8);
        }
    }

    float o[8][4];
#pragma unroll
    for (int i = 0; i < 8; i++)
#pragma unroll
        for (int j = 0; j < 4; j++) o[i][j] = 0.0f;
    float l0 = 0.0f, l1 = 0.0f;

    int mreg = 0;
    if (tid < 64) mreg = mask[(size_t)b * S_ + tid];

    {
        uint32_t dK = sptr(&KtB[(size_t)key * FKP + dg]);
        uint32_t dV = sptr(&VsB[(size_t)key * FKP + dg]);
        const __half* sK = Kg0 + (size_t)key * DK + dg;
        const __half* sV = Vg0 + (size_t)key * DK + dg;
        cp16(dK, sK); cp16(dK + 16, sK + 8);
        cp16(dV, sV); cp16(dV + 16, sV + 8);
        cp_commit();
    }

    for (int t = 0; t < NT; t++) {
        const int kb64 = t * 64;
        const int buf = (t & 1) * 64;

        __syncthreads();
        if (tid < 64) msk[tid] = mreg;
        if (t + 1 < NT) {
            const int nbuf = ((t + 1) & 1) * 64;
            uint32_t dK = sptr(&KtB[(size_t)(nbuf + key) * FKP + dg]);
            uint32_t dV = sptr(&VsB[(size_t)(nbuf + key) * FKP + dg]);
            const __half* sK = Kg0 + (size_t)(kb64 + 64 + key) * DK + dg;
            const __half* sV = Vg0 + (size_t)(kb64 + 64 + key) * DK + dg;
            cp16(dK, sK); cp16(dK + 16, sK + 8);
            cp16(dV, sV); cp16(dV + 16, sV + 8);
            cp_commit();
            if (tid < 64) mreg = mask[(size_t)b * S_ + kb64 + 64 + tid];
            cp_wait<1>();
        } else {
            cp_wait<0>();
        }
        __syncthreads();

        // ---- S = Q K^T ----
        float s[8][4];
#pragma unroll
        for (int i = 0; i < 8; i++)
#pragma unroll
            for (int j = 0; j < 4; j++) s[i][j] = 0.0f;

#pragma unroll
        for (int j = 0; j < 4; j++) {
            const int kb = j * 16;
#pragma unroll
            for (int p = 0; p < 4; p++) {
                uint32_t bf[4];
                ldsm4(bf, sptr(&KtB[(size_t)(buf + p * 16 + brow) * FKP + kb + bcol]));
                mma_f16(s[2 * p],     qa[j], bf[0], bf[1]);
                mma_f16(s[2 * p + 1], qa[j], bf[2], bf[3]);
            }
        }

        // ---- p = mask ? exp(s*scale) : 0 ----
        float ss0 = 0.0f, ss1 = 0.0f;
#pragma unroll
        for (int ns = 0; ns < 8; ns++) {
            int c0 = ns * 8 + 2 * tq;
            int mk0 = msk[c0], mk1 = msk[c0 + 1];
            s[ns][0] = mk0 ? __expf(s[ns][0] * SCALEF) : 0.0f;
            s[ns][1] = mk1 ? __expf(s[ns][1] * SCALEF) : 0.0f;
            s[ns][2] = mk0 ? __expf(s[ns][2] * SCALEF) : 0.0f;
            s[ns][3] = mk1 ? __expf(s[ns][3] * SCALEF) : 0.0f;
            ss0 += s[ns][0] + s[ns][1];
            ss1 += s[ns][2] + s[ns][3];
        }
        ss0 += __shfl_xor_sync(0xffffffffu, ss0, 1);
        ss0 += __shfl_xor_sync(0xffffffffu, ss0, 2);
        ss1 += __shfl_xor_sync(0xffffffffu, ss1, 1);
        ss1 += __shfl_xor_sync(0xffffffffu, ss1, 2);
        l0 += ss0;
        l1 += ss1;

        // ---- P fragments ----
        uint32_t pa[4][4];
#pragma unroll
        for (int j = 0; j < 4; j++) {
            pa[j][0] = h2pack(s[2 * j][0], s[2 * j][1]);
            pa[j][1] = h2pack(s[2 * j][2], s[2 * j][3]);
            pa[j][2] = h2pack(s[2 * j + 1][0], s[2 * j + 1][1]);
            pa[j][3] = h2pack(s[2 * j + 1][2], s[2 * j + 1][3]);
        }

        // stage p into Sst (warp-local rows)
#pragma unroll
        for (int j = 0; j < 4; j++) {
            *(uint32_t*)&Sst[(size_t)(w * 16 + gid) * FKP + (2 * j) * 8 + 2 * tq]     = pa[j][0];
            *(uint32_t*)&Sst[(size_t)(w * 16 + gid) * FKP + (2 * j + 1) * 8 + 2 * tq] = pa[j][2];
            *(uint32_t*)&Sst[(size_t)(w * 16 + gid + 8) * FKP + (2 * j) * 8 + 2 * tq]     = pa[j][1];
            *(uint32_t*)&Sst[(size_t)(w * 16 + gid + 8) * FKP + (2 * j + 1) * 8 + 2 * tq] = pa[j][3];
        }
        __syncthreads();

        // cooperative coalesced store of p tile
#pragma unroll
        for (int i = 0; i < 4; i++) {
            int idx = tid + i * 256;
            int row = idx >> 3;
            int c8 = (idx & 7) * 8;
            uint4 v = *(uint4*)&Sst[(size_t)row * FKP + c8];
            *(uint4*)(g_S + (bh * S_ + qb + row) * S_ + kb64 + c8) = v;
        }

        // ---- O += P V ----
#pragma unroll
        for (int j = 0; j < 4; j++) {
#pragma unroll
            for (int p = 0; p < 4; p++) {
                uint32_t vf[4];
                ldsm4t(vf, sptr(&VsB[(size_t)(buf + j * 16 + vrow) * FKP + p * 16 + vcol]));
                mma_f16(o[2 * p],     pa[j], vf[0], vf[1]);
                mma_f16(o[2 * p + 1], pa[j], vf[2], vf[3]);
            }
        }
    }

    float inv0 = 1.0f / l0, inv1 = 1.0f / l1;
#pragma unroll
    for (int ds = 0; ds < 8; ds++) {
        int dv = ds * 8 + tq * 2;
        __half* p0 = g_ctx + (((size_t)b * S_ + rowq0) * H_ + h) * DK + dv;
        __half* p1 = g_ctx + (((size_t)b * S_ + rowq0 + 8) * H_ + h) * DK + dv;
        *(uint32_t*)p0 = h2pack(o[ds][0] * inv0, o[ds][1] * inv0);
        *(uint32_t*)p1 = h2pack(o[ds][2] * inv1, o[ds][3] * inv1);
    }
    if (tq == 0) {
        g_l[bh * S_ + rowq0] = l0;
        g_l[bh * S_ + rowq0 + 8] = l1;
    }
}

// ============================================================
// Mean over heads: pure streaming p * (1/l), no exp.
// ============================================================
__global__ __launch_bounds__(256)
void mean_pass(float* __restrict__ outm)
{
    __shared__ float sl[H_];
    const int tid = threadIdx.x;
    const int q = blockIdx.x;
    const int b = blockIdx.y;

    if (tid < H_)
        sl[tid] = 1.0f / g_l[((size_t)b * H_ + tid) * S_ + q];
    __syncthreads();

    const int k0 = tid * 8;
    float acc[8];
#pragma unroll
    for (int i = 0; i < 8; i++) acc[i] = 0.0f;

    for (int h = 0; h < H_; h++) {
        const __half* Sp = g_S + (((size_t)b * H_ + h) * S_ + q) * S_ + k0;
        uint4 raw = *(const uint4*)Sp;
        const __half2* hp = (const __half2*)&raw;
        float lih = sl[h];
#pragma unroll
        for (int i = 0; i < 4; i++) {
            float2 v = __half22float2(hp[i]);
            acc[2 * i + 0] += v.x * lih;
            acc[2 * i + 1] += v.y * lih;
        }
    }

    const float invH = 1.0f / (float)H_;
    float* op = outm + ((size_t)b * S_ + q) * S_ + k0;
    *(float4*)op = make_float4(acc[0]*invH, acc[1]*invH, acc[2]*invH, acc[3]*invH);
    *(float4*)(op + 4) = make_float4(acc[4]*invH, acc[5]*invH, acc[6]*invH, acc[7]*invH);
}

// ============================================================
extern "C" void kernel_launch(void* const* d_in, const int* in_sizes, int n_in,
                              void* d_out, int out_size)
{
    const float* query = (const float*)d_in[0];
    const float* keyt  = (const float*)d_in[1];
    const float* value = (const float*)d_in[2];
    const int*   mask  = (const int*)d_in[3];
    const float* Wq    = (const float*)d_in[4];
    const float* Wk    = (const float*)d_in[5];
    const float* Wv    = (const float*)d_in[6];
    const float* Wo    = (const float*)d_in[7];
    const float* bo    = (const float*)d_in[8];
    float* out = (float*)d_out;

    cudaFuncSetAttribute(flash_f16,
                         cudaFuncAttributeMaxDynamicSharedMemorySize, FLASH_SMEM);

    __half *wh3, *ctxp;
    cudaGetSymbolAddress((void**)&wh3, g_Wh);
    wh3 += 3 * (size_t)DM * DM;
    cudaGetSymbolAddress((void**)&ctxp, g_ctx);

    const int nX8 = (B_ * S_ * DM) / 8;
    const int nW8 = (DM * DM) / 8;
    f2hX_kernel<<<dim3((nX8 + 255) / 256, 3), 256>>>(query, keyt, value, nX8);
    f2hW_kernel<<<dim3((nW8 + 255) / 256, 4), 256>>>(Wq, Wk, Wv, Wo, nW8);

    // fused 3-projection launch (blockIdx.z selects X/W/dest)
    gemm_h<0><<<dim3(DM / 128, (B_ * S_) / 128, 3), 256>>>(nullptr, nullptr, nullptr, nullptr);

    flash_f16<<<dim3(S_ / 128, H_, B_), 256, FLASH_SMEM>>>(mask);

    gemm_h<1><<<dim3(DM / 128, (B_ * S_) / 128), 256>>>(ctxp, wh3, bo, out);

    long long need = (long long)B_ * S_ * DM + (long long)B_ * S_ * S_;
    if ((long long)out_size >= need) {
        mean_pass<<<dim3(S_, B_), 256>>>(out + (size_t)B_ * S_ * DM);
    }
}

// round 16
// speedup vs baseline: 1.5868x; 1.0594x over previous
#include <cuda_runtime.h>
#include <cuda_fp16.h>
#include <stdint.h>

#define B_  4
#define S_  2048
#define DM  1024
#define H_  16
#define DK  64
#define SCALEF 0.125f
#define SC2   (0.125f * 1.44269504088896f)   // SCALEF * log2(e)

// ---- device scratch (no runtime allocation allowed) ----
__device__ __half g_Q[(size_t)B_*H_*S_*DK];
__device__ __half g_K[(size_t)B_*H_*S_*DK];
__device__ __half g_V[(size_t)B_*H_*S_*DK];
__device__ __half g_ctx[(size_t)B_*S_*DM];
__device__ float  g_l[(size_t)B_*H_*S_];
__device__ __half g_S[(size_t)B_*H_*S_*S_];     // UNNORMALIZED probs exp(s)
__device__ __half g_Xh[3][(size_t)B_*S_*DM];    // half inputs
__device__ __half g_Wh[4][(size_t)DM*DM];       // half weights

// ---------- helpers ----------
__device__ __forceinline__ uint32_t h2pack(float x, float y) {
    __half2 h = __floats2half2_rn(x, y);
    return *(uint32_t*)&h;
}
__device__ __forceinline__ float fexp2(float x) {
    float y;
    asm("ex2.approx.ftz.f32 %0, %1;" : "=f"(y) : "f"(x));
    return y;
}
__device__ __forceinline__ uint32_t sptr(const void* p) {
    return (uint32_t)__cvta_generic_to_shared(p);
}
__device__ __forceinline__ void ldsm4(uint32_t* r, uint32_t addr) {
    asm volatile("ldmatrix.sync.aligned.m8n8.x4.shared.b16 {%0,%1,%2,%3}, [%4];"
        : "=r"(r[0]), "=r"(r[1]), "=r"(r[2]), "=r"(r[3]) : "r"(addr));
}
__device__ __forceinline__ void ldsm4t(uint32_t* r, uint32_t addr) {
    asm volatile("ldmatrix.sync.aligned.m8n8.x4.trans.shared.b16 {%0,%1,%2,%3}, [%4];"
        : "=r"(r[0]), "=r"(r[1]), "=r"(r[2]), "=r"(r[3]) : "r"(addr));
}
__device__ __forceinline__ void cp16(uint32_t dst, const void* src) {
    asm volatile("cp.async.cg.shared.global [%0], [%1], 16;" :: "r"(dst), "l"(src));
}
__device__ __forceinline__ void cp_commit() {
    asm volatile("cp.async.commit_group;");
}
template <int N>
__device__ __forceinline__ void cp_wait() {
    asm volatile("cp.async.wait_group %0;" :: "n"(N));
}
__device__ __forceinline__ void mma_f16(float* c, const uint32_t* a,
                                        uint32_t b0, uint32_t b1)
{
    asm volatile(
        "mma.sync.aligned.m16n8k16.row.col.f32.f16.f16.f32 "
        "{%0,%1,%2,%3}, {%4,%5,%6,%7}, {%8,%9}, {%0,%1,%2,%3};\n"
        : "+f"(c[0]), "+f"(c[1]), "+f"(c[2]), "+f"(c[3])
        : "r"(a[0]), "r"(a[1]), "r"(a[2]), "r"(a[3]), "r"(b0), "r"(b1));
}

// ============================================================
// fp32 -> fp16 converts, batched (blockIdx.y selects tensor)
// ============================================================
__global__ __launch_bounds__(256)
void f2hX_kernel(const float* __restrict__ q, const float* __restrict__ k,
                 const float* __restrict__ v, int n8)
{
    int i = blockIdx.x * 256 + threadIdx.x;
    if (i >= n8) return;
    int which = blockIdx.y;
    const float* src = (which == 0) ? q : (which == 1) ? k : v;
    __half* dst = g_Xh[which];
    const float4* s = (const float4*)(src) + 2 * i;
    float4 a = s[0], b = s[1];
    uint4 o;
    o.x = h2pack(a.x, a.y); o.y = h2pack(a.z, a.w);
    o.z = h2pack(b.x, b.y); o.w = h2pack(b.z, b.w);
    *((uint4*)(dst) + i) = o;
}
__global__ __launch_bounds__(256)
void f2hW_kernel(const float* __restrict__ w0, const float* __restrict__ w1,
                 const float* __restrict__ w2, const float* __restrict__ w3, int n8)
{
    int i = blockIdx.x * 256 + threadIdx.x;
    if (i >= n8) return;
    int which = blockIdx.y;
    const float* src = (which == 0) ? w0 : (which == 1) ? w1
                     : (which == 2) ? w2 : w3;
    __half* dst = g_Wh[which];
    const float4* s = (const float4*)(src) + 2 * i;
    float4 a = s[0], b = s[1];
    uint4 o;
    o.x = h2pack(a.x, a.y); o.y = h2pack(a.z, a.w);
    o.z = h2pack(b.x, b.y); o.w = h2pack(b.z, b.w);
    *((uint4*)(dst) + i) = o;
}

// ============================================================
// half GEMM (R12-proven 2-stage): 128x128, cp.async dbuf.
// MODE 0: fused 3-projection launch; blockIdx.z selects X/W/dest.
// MODE 1: g_ctx @ Wo^T -> fp32 out + bias
// ============================================================
#define KP 40
#define NKT (DM / 32)
template <int MODE>
__global__ __launch_bounds__(256)
void gemm_h(const __half* __restrict__ Xp, const __half* __restrict__ Wp,
            const float* __restrict__ bias, float* __restrict__ Yout)
{
    __shared__ __half Xs[2][128][KP];
    __shared__ __half Ws[2][128][KP];

    const int tid = threadIdx.x;
    const int lane = tid & 31;
    const int gid = lane >> 2;
    const int tq  = lane & 3;
    const int lrow = lane & 7;
    const int lmat = lane >> 3;
    const int wid = tid >> 5;
    const int wm = (wid >> 2) * 64;
    const int wn = (wid & 3) * 32;
    const int m0 = blockIdx.y * 128;
    const int n0 = blockIdx.x * 128;
    const int dest = (MODE == 0) ? blockIdx.z : 3;

    const __half* X = (MODE == 0) ? g_Xh[dest] : Xp;
    const __half* W = (MODE == 0) ? g_Wh[dest] : Wp;

    const int arow = (lmat & 1) * 8 + lrow;
    const int acol = (lmat >> 1) * 8;
    const int brow = (lmat >> 1) * 8 + lrow;
    const int bcol = (lmat & 1) * 8;

    const int lr0 = tid >> 2;
    const int lc0 = (tid & 3) * 8;
    const int lr1 = lr0 + 64;

    float acc[4][4][4];
#pragma unroll
    for (int i = 0; i < 4; i++)
#pragma unroll
        for (int j = 0; j < 4; j++)
#pragma unroll
            for (int e = 0; e < 4; e++) acc[i][j][e] = 0.0f;

    const __half* Xb = X + (size_t)m0 * DM;
    const __half* Wb = W + (size_t)n0 * DM;

    {
        cp16(sptr(&Xs[0][lr0][lc0]), Xb + (size_t)lr0 * DM + lc0);
        cp16(sptr(&Xs[0][lr1][lc0]), Xb + (size_t)lr1 * DM + lc0);
        cp16(sptr(&Ws[0][lr0][lc0]), Wb + (size_t)lr0 * DM + lc0);
        cp16(sptr(&Ws[0][lr1][lc0]), Wb + (size_t)lr1 * DM + lc0);
        cp_commit();
    }

    for (int t = 0; t < NKT; t++) {
        const int buf = t & 1;
        __syncthreads();
        if (t + 1 < NKT) {
            const int nb = buf ^ 1;
            const int k1 = (t + 1) * 32;
            cp16(sptr(&Xs[nb][lr0][lc0]), Xb + (size_t)lr0 * DM + k1 + lc0);
            cp16(sptr(&Xs[nb][lr1][lc0]), Xb + (size_t)lr1 * DM + k1 + lc0);
            cp16(sptr(&Ws[nb][lr0][lc0]), Wb + (size_t)lr0 * DM + k1 + lc0);
            cp16(sptr(&Ws[nb][lr1][lc0]), Wb + (size_t)lr1 * DM + k1 + lc0);
            cp_commit();
            cp_wait<1>();
        } else {
            cp_wait<0>();
        }
        __syncthreads();

#pragma unroll
        for (int k16 = 0; k16 < 2; k16++) {
            const int kb = k16 * 16;
            uint32_t a[4][4], bf[2][4];
#pragma unroll
            for (int ms = 0; ms < 4; ms++)
                ldsm4(a[ms], sptr(&Xs[buf][wm + ms * 16 + arow][kb + acol]));
#pragma unroll
            for (int p = 0; p < 2; p++)
                ldsm4(bf[p], sptr(&Ws[buf][wn + p * 16 + brow][kb + bcol]));
#pragma unroll
            for (int ms = 0; ms < 4; ms++)
#pragma unroll
                for (int p = 0; p < 2; p++) {
                    mma_f16(acc[ms][2 * p],     a[ms], bf[p][0], bf[p][1]);
                    mma_f16(acc[ms][2 * p + 1], a[ms], bf[p][2], bf[p][3]);
                }
        }
    }

    if (MODE == 0) {
        __half* Dst = (dest == 0) ? g_Q : (dest == 1) ? g_K : g_V;
#pragma unroll
        for (int ms = 0; ms < 4; ms++) {
            int r0 = m0 + wm + ms * 16 + gid;
#pragma unroll
            for (int ns = 0; ns < 4; ns++) {
                int n = n0 + wn + ns * 8 + tq * 2;
                int h = n >> 6, dk = n & 63;
                {
                    int m = r0;
                    int b = m >> 11, s = m & 2047;
                    __half* p = Dst + (((size_t)b * H_ + h) * S_ + s) * DK + dk;
                    *(uint32_t*)p = h2pack(acc[ms][ns][0], acc[ms][ns][1]);
                }
                {
                    int m = r0 + 8;
                    int b = m >> 11, s = m & 2047;
                    __half* p = Dst + (((size_t)b * H_ + h) * S_ + s) * DK + dk;
                    *(uint32_t*)p = h2pack(acc[ms][ns][2], acc[ms][ns][3]);
                }
            }
        }
    } else {
#pragma unroll
        for (int ms = 0; ms < 4; ms++) {
            int r0 = m0 + wm + ms * 16 + gid;
#pragma unroll
            for (int ns = 0; ns < 4; ns++) {
                int n = n0 + wn + ns * 8 + tq * 2;
                float b0 = bias[n], b1 = bias[n + 1];
                *(float2*)(Yout + (size_t)r0 * DM + n) =
                    make_float2(acc[ms][ns][0] + b0, acc[ms][ns][1] + b1);
                *(float2*)(Yout + (size_t)(r0 + 8) * DM + n) =
                    make_float2(acc[ms][ns][2] + b0, acc[ms][ns][3] + b1);
            }
        }
    }
}

// ============================================================
// Flash attention v4: no max; l via MMA with constant ones-B;
// exp via single ex2.approx. Stores p to g_S.
// ============================================================
#define FKP 72
#define NT  (S_ / 64)
#define SM_K   0
#define SM_V   (2 * 64 * FKP)
#define SM_S   (4 * 64 * FKP)
#define SM_MSK (4 * 64 * FKP + 128 * FKP)
#define FLASH_SMEM (SM_MSK * 2 + 64 * 4)
#define ONES2 0x3C003C00u    // half2(1.0, 1.0)

__global__ __launch_bounds__(256, 2)
void flash_f16(const int* __restrict__ mask)
{
    extern __shared__ __half smh[];
    __half* KtB = smh + SM_K;
    __half* VsB = smh + SM_V;
    __half* Sst = smh + SM_S;
    int*    msk = (int*)(smh + SM_MSK);

    const int tid = threadIdx.x;
    const int lane = tid & 31;
    const int gid = lane >> 2;
    const int tq  = lane & 3;
    const int lrow = lane & 7;
    const int lmat = lane >> 3;
    const int w   = tid >> 5;
    const int qb  = blockIdx.x * 128;
    const int h   = blockIdx.y;
    const int b   = blockIdx.z;

    const int rowq0 = qb + w * 16 + gid;
    const size_t bh = (size_t)b * H_ + h;

    const int brow = (lmat >> 1) * 8 + lrow;
    const int bcol = (lmat & 1) * 8;
    const int vrow = (lmat & 1) * 8 + lrow;
    const int vcol = (lmat >> 1) * 8;

    const int key = tid >> 2;
    const int dg  = (tid & 3) * 16;

    const __half* Kg0 = g_K + bh * S_ * DK;
    const __half* Vg0 = g_V + bh * S_ * DK;

    uint32_t qa[4][4];
    {
        const __half* Qg = g_Q + (bh * S_ + qb + w * 16) * DK;
#pragma unroll
        for (int j = 0; j < 4; j++) {
            int c = j * 16 + 2 * tq;
            qa[j][0] = *(const uint32_t*)(Qg + (size_t)gid * DK + c);
            qa[j][1] = *(const uint32_t*)(Qg + (size_t)(gid + 8) * DK + c);
            qa[j][2] = *(const uint32_t*)(Qg + (size_t)gid * DK + c + 8);
            qa[j][3] = *(const uint32_t*)(Qg + (size_t)(gid + 8) * DK + c + 8);
        }
    }

    float o[8][4];
#pragma unroll
    for (int i = 0; i < 8; i++)
#pragma unroll
        for (int j = 0; j < 4; j++) o[i][j] = 0.0f;
    float lsum[4] = {0.0f, 0.0f, 0.0f, 0.0f};   // P @ ones accumulator

    int mreg = 0;
    if (tid < 64) mreg = mask[(size_t)b * S_ + tid];

    {
        uint32_t dK = sptr(&KtB[(size_t)key * FKP + dg]);
        uint32_t dV = sptr(&VsB[(size_t)key * FKP + dg]);
        const __half* sK = Kg0 + (size_t)key * DK + dg;
        const __half* sV = Vg0 + (size_t)key * DK + dg;
        cp16(dK, sK); cp16(dK + 16, sK + 8);
        cp16(dV, sV); cp16(dV + 16, sV + 8);
        cp_commit();
    }

    for (int t = 0; t < NT; t++) {
        const int kb64 = t * 64;
        const int buf = (t & 1) * 64;

        __syncthreads();
        if (tid < 64) msk[tid] = mreg;
        if (t + 1 < NT) {
            const int nbuf = ((t + 1) & 1) * 64;
            uint32_t dK = sptr(&KtB[(size_t)(nbuf + key) * FKP + dg]);
            uint32_t dV = sptr(&VsB[(size_t)(nbuf + key) * FKP + dg]);
            const __half* sK = Kg0 + (size_t)(kb64 + 64 + key) * DK + dg;
            const __half* sV = Vg0 + (size_t)(kb64 + 64 + key) * DK + dg;
            cp16(dK, sK); cp16(dK + 16, sK + 8);
            cp16(dV, sV); cp16(dV + 16, sV + 8);
            cp_commit();
            if (tid < 64) mreg = mask[(size_t)b * S_ + kb64 + 64 + tid];
            cp_wait<1>();
        } else {
            cp_wait<0>();
        }
        __syncthreads();

        // ---- S = Q K^T ----
        float s[8][4];
#pragma unroll
        for (int i = 0; i < 8; i++)
#pragma unroll
            for (int j = 0; j < 4; j++) s[i][j] = 0.0f;

#pragma unroll
        for (int j = 0; j < 4; j++) {
            const int kb = j * 16;
#pragma unroll
            for (int p = 0; p < 4; p++) {
                uint32_t bf[4];
                ldsm4(bf, sptr(&KtB[(size_t)(buf + p * 16 + brow) * FKP + kb + bcol]));
                mma_f16(s[2 * p],     qa[j], bf[0], bf[1]);
                mma_f16(s[2 * p + 1], qa[j], bf[2], bf[3]);
            }
        }

        // ---- p = mask ? exp2(s*SC2) : 0  (single MUFU path) ----
#pragma unroll
        for (int ns = 0; ns < 8; ns++) {
            int c0 = ns * 8 + 2 * tq;
            int mk0 = msk[c0], mk1 = msk[c0 + 1];
            s[ns][0] = mk0 ? fexp2(s[ns][0] * SC2) : 0.0f;
            s[ns][1] = mk1 ? fexp2(s[ns][1] * SC2) : 0.0f;
            s[ns][2] = mk0 ? fexp2(s[ns][2] * SC2) : 0.0f;
            s[ns][3] = mk1 ? fexp2(s[ns][3] * SC2) : 0.0f;
        }

        // ---- P fragments (values stored to g_S and used by both MMAs) ----
        uint32_t pa[4][4];
#pragma unroll
        for (int j = 0; j < 4; j++) {
            pa[j][0] = h2pack(s[2 * j][0], s[2 * j][1]);
            pa[j][1] = h2pack(s[2 * j][2], s[2 * j][3]);
            pa[j][2] = h2pack(s[2 * j + 1][0], s[2 * j + 1][1]);
            pa[j][3] = h2pack(s[2 * j + 1][2], s[2 * j + 1][3]);
        }

        // ---- l += P @ ones (constant B fragment, no smem, no shuffles) ----
#pragma unroll
        for (int j = 0; j < 4; j++)
            mma_f16(lsum, pa[j], ONES2, ONES2);

        // stage p into Sst (warp-local rows)
#pragma unroll
        for (int j = 0; j < 4; j++) {
            *(uint32_t*)&Sst[(size_t)(w * 16 + gid) * FKP + (2 * j) * 8 + 2 * tq]     = pa[j][0];
            *(uint32_t*)&Sst[(size_t)(w * 16 + gid) * FKP + (2 * j + 1) * 8 + 2 * tq] = pa[j][2];
            *(uint32_t*)&Sst[(size_t)(w * 16 + gid + 8) * FKP + (2 * j) * 8 + 2 * tq]     = pa[j][1];
            *(uint32_t*)&Sst[(size_t)(w * 16 + gid + 8) * FKP + (2 * j + 1) * 8 + 2 * tq] = pa[j][3];
        }
        __syncthreads();

        // cooperative coalesced store of p tile
#pragma unroll
        for (int i = 0; i < 4; i++) {
            int idx = tid + i * 256;
            int row = idx >> 3;
            int c8 = (idx & 7) * 8;
            uint4 v = *(uint4*)&Sst[(size_t)row * FKP + c8];
            *(uint4*)(g_S + (bh * S_ + qb + row) * S_ + kb64 + c8) = v;
        }

        // ---- O += P V ----
#pragma unroll
        for (int j = 0; j < 4; j++) {
#pragma unroll
            for (int p = 0; p < 4; p++) {
                uint32_t vf[4];
                ldsm4t(vf, sptr(&VsB[(size_t)(buf + j * 16 + vrow) * FKP + p * 16 + vcol]));
                mma_f16(o[2 * p],     pa[j], vf[0], vf[1]);
                mma_f16(o[2 * p + 1], pa[j], vf[2], vf[3]);
            }
        }
    }

    const float l0 = lsum[0], l1 = lsum[2];
    float inv0 = 1.0f / l0, inv1 = 1.0f / l1;
#pragma unroll
    for (int ds = 0; ds < 8; ds++) {
        int dv = ds * 8 + tq * 2;
        __half* p0 = g_ctx + (((size_t)b * S_ + rowq0) * H_ + h) * DK + dv;
        __half* p1 = g_ctx + (((size_t)b * S_ + rowq0 + 8) * H_ + h) * DK + dv;
        *(uint32_t*)p0 = h2pack(o[ds][0] * inv0, o[ds][1] * inv0);
        *(uint32_t*)p1 = h2pack(o[ds][2] * inv1, o[ds][3] * inv1);
    }
    if (tq == 0) {
        g_l[bh * S_ + rowq0] = l0;
        g_l[bh * S_ + rowq0 + 8] = l1;
    }
}

// ============================================================
// Mean over heads: pure streaming p * (1/l), no exp.
// ============================================================
__global__ __launch_bounds__(256)
void mean_pass(float* __restrict__ outm)
{
    __shared__ float sl[H_];
    const int tid = threadIdx.x;
    const int q = blockIdx.x;
    const int b = blockIdx.y;

    if (tid < H_)
        sl[tid] = 1.0f / g_l[((size_t)b * H_ + tid) * S_ + q];
    __syncthreads();

    const int k0 = tid * 8;
    float acc[8];
#pragma unroll
    for (int i = 0; i < 8; i++) acc[i] = 0.0f;

    for (int h = 0; h < H_; h++) {
        const __half* Sp = g_S + (((size_t)b * H_ + h) * S_ + q) * S_ + k0;
        uint4 raw = *(const uint4*)Sp;
        const __half2* hp = (const __half2*)&raw;
        float lih = sl[h];
#pragma unroll
        for (int i = 0; i < 4; i++) {
            float2 v = __half22float2(hp[i]);
            acc[2 * i + 0] += v.x * lih;
            acc[2 * i + 1] += v.y * lih;
        }
    }

    const float invH = 1.0f / (float)H_;
    float* op = outm + ((size_t)b * S_ + q) * S_ + k0;
    *(float4*)op = make_float4(acc[0]*invH, acc[1]*invH, acc[2]*invH, acc[3]*invH);
    *(float4*)(op + 4) = make_float4(acc[4]*invH, acc[5]*invH, acc[6]*invH, acc[7]*invH);
}

// ============================================================
extern "C" void kernel_launch(void* const* d_in, const int* in_sizes, int n_in,
                              void* d_out, int out_size)
{
    const float* query = (const float*)d_in[0];
    const float* keyt  = (const float*)d_in[1];
    const float* value = (const float*)d_in[2];
    const int*   mask  = (const int*)d_in[3];
    const float* Wq    = (const float*)d_in[4];
    const float* Wk    = (const float*)d_in[5];
    const float* Wv    = (const float*)d_in[6];
    const float* Wo    = (const float*)d_in[7];
    const float* bo    = (const float*)d_in[8];
    float* out = (float*)d_out;

    cudaFuncSetAttribute(flash_f16,
                         cudaFuncAttributeMaxDynamicSharedMemorySize, FLASH_SMEM);

    __half *wh3, *ctxp;
    cudaGetSymbolAddress((void**)&wh3, g_Wh);
    wh3 += 3 * (size_t)DM * DM;
    cudaGetSymbolAddress((void**)&ctxp, g_ctx);

    const int nX8 = (B_ * S_ * DM) / 8;
    const int nW8 = (DM * DM) / 8;
    f2hX_kernel<<<dim3((nX8 + 255) / 256, 3), 256>>>(query, keyt, value, nX8);
    f2hW_kernel<<<dim3((nW8 + 255) / 256, 4), 256>>>(Wq, Wk, Wv, Wo, nW8);

    // fused 3-projection launch (blockIdx.z selects X/W/dest)
    gemm_h<0><<<dim3(DM / 128, (B_ * S_) / 128, 3), 256>>>(nullptr, nullptr, nullptr, nullptr);

    flash_f16<<<dim3(S_ / 128, H_, B_), 256, FLASH_SMEM>>>(mask);

    gemm_h<1><<<dim3(DM / 128, (B_ * S_) / 128), 256>>>(ctxp, wh3, bo, out);

    long long need = (long long)B_ * S_ * DM + (long long)B_ * S_ * S_;
    if ((long long)out_size >= need) {
        mean_pass<<<dim3(S_, B_), 256>>>(out + (size_t)B_ * S_ * DM);
    }
}